// round 5
// baseline (speedup 1.0000x reference)
#include <cuda_runtime.h>
#include <cuda_bf16.h>
#include <math.h>
#include <stdint.h>

#define B_ 2
#define T_ 2048
#define DIM_ 2048
#define H_ 16
#define HD_ 128
#define BT_ (B_ * T_)

// Scratch (alloc-free rules: __device__ globals)
static __device__ float g_q[(size_t)BT_ * DIM_];     // Q after GEMM+RoPE, [B,T,H,HD]
static __device__ float g_attn[(size_t)BT_ * DIM_];  // attention out, [B,T,DIM]

// ---------------------------------------------------------------------------
// TF32 helpers (R2, proven)
// ---------------------------------------------------------------------------
__device__ __forceinline__ uint32_t f2tf(float x) {
    uint32_t r;
    asm("cvt.rna.tf32.f32 %0, %1;" : "=r"(r) : "f"(x));
    return r;
}

__device__ __forceinline__ void mma8(float* c, uint32_t a0, uint32_t a1, uint32_t a2,
                                     uint32_t a3, uint32_t b0, uint32_t b1) {
    asm volatile(
        "mma.sync.aligned.m16n8k8.row.col.f32.tf32.tf32.f32 "
        "{%0,%1,%2,%3},{%4,%5,%6,%7},{%8,%9},{%0,%1,%2,%3};"
        : "+f"(c[0]), "+f"(c[1]), "+f"(c[2]), "+f"(c[3])
        : "r"(a0), "r"(a1), "r"(a2), "r"(a3), "r"(b0), "r"(b1));
}

// bf16 m16n8k16 mma
__device__ __forceinline__ void mmabf(float* c, uint32_t a0, uint32_t a1, uint32_t a2,
                                      uint32_t a3, uint32_t b0, uint32_t b1) {
    asm volatile(
        "mma.sync.aligned.m16n8k16.row.col.f32.bf16.bf16.f32 "
        "{%0,%1,%2,%3},{%4,%5,%6,%7},{%8,%9},{%0,%1,%2,%3};"
        : "+f"(c[0]), "+f"(c[1]), "+f"(c[2]), "+f"(c[3])
        : "r"(a0), "r"(a1), "r"(a2), "r"(a3), "r"(b0), "r"(b1));
}

__device__ __forceinline__ uint32_t pack_hi(float a, float b) {
    __nv_bfloat162 p = __floats2bfloat162_rn(a, b);
    return *(uint32_t*)&p;
}

// ---------------------------------------------------------------------------
// TF32 tensor-core GEMM (unchanged from R2)
// ---------------------------------------------------------------------------
__global__ __launch_bounds__(256) void tgemm(
    const float* __restrict__ A, const float* __restrict__ Bm, float* __restrict__ C,
    int M, int N, int K, int asel, int csel)
{
    if (asel == 1) A = g_attn;
    if (csel == 1) C = g_q;

    __shared__ uint32_t As[16][136];
    __shared__ uint32_t Bs[16][136];

    int tid = threadIdx.x;
    int bn0 = blockIdx.x * 128, bm0 = blockIdx.y * 128;
    int warp = tid >> 5, lane = tid & 31;
    int wm = (warp & 1) * 64, wn = (warp >> 1) * 32;
    int lr = lane >> 2, lc = lane & 3;

    float acc[4][4][4];
#pragma unroll
    for (int mt = 0; mt < 4; mt++)
#pragma unroll
        for (int nt = 0; nt < 4; nt++)
#pragma unroll
            for (int i = 0; i < 4; i++) acc[mt][nt][i] = 0.f;

    int ar = tid >> 2, ac = (tid & 3) << 2;
    int br = tid >> 5, bc = (tid & 31) << 2;

    const float* Ap = A + (size_t)(bm0 + ar) * K + ac;
    const float* Bp = Bm + (size_t)br * N + bn0 + bc;

    for (int k0 = 0; k0 < K; k0 += 16) {
        float4 a0v = *(const float4*)(Ap);
        float4 a1v = *(const float4*)(Ap + (size_t)64 * K);
        float4 b0v = *(const float4*)(Bp);
        float4 b1v = *(const float4*)(Bp + (size_t)8 * N);
        __syncthreads();

        As[ac + 0][ar] = f2tf(a0v.x); As[ac + 1][ar] = f2tf(a0v.y);
        As[ac + 2][ar] = f2tf(a0v.z); As[ac + 3][ar] = f2tf(a0v.w);
        As[ac + 0][ar + 64] = f2tf(a1v.x); As[ac + 1][ar + 64] = f2tf(a1v.y);
        As[ac + 2][ar + 64] = f2tf(a1v.z); As[ac + 3][ar + 64] = f2tf(a1v.w);
        *(uint4*)&Bs[br][bc]     = make_uint4(f2tf(b0v.x), f2tf(b0v.y), f2tf(b0v.z), f2tf(b0v.w));
        *(uint4*)&Bs[br + 8][bc] = make_uint4(f2tf(b1v.x), f2tf(b1v.y), f2tf(b1v.z), f2tf(b1v.w));
        __syncthreads();

#pragma unroll
        for (int kk = 0; kk < 16; kk += 8) {
            uint32_t bf[4][2];
#pragma unroll
            for (int nt = 0; nt < 4; nt++) {
                bf[nt][0] = Bs[kk + lc][wn + nt * 8 + lr];
                bf[nt][1] = Bs[kk + lc + 4][wn + nt * 8 + lr];
            }
#pragma unroll
            for (int mt = 0; mt < 4; mt++) {
                uint32_t a0 = As[kk + lc][wm + mt * 16 + lr];
                uint32_t a1 = As[kk + lc][wm + mt * 16 + lr + 8];
                uint32_t a2 = As[kk + lc + 4][wm + mt * 16 + lr];
                uint32_t a3 = As[kk + lc + 4][wm + mt * 16 + lr + 8];
#pragma unroll
                for (int nt = 0; nt < 4; nt++)
                    mma8(acc[mt][nt], a0, a1, a2, a3, bf[nt][0], bf[nt][1]);
            }
        }
        Ap += 16;
        Bp += (size_t)16 * N;
    }

#pragma unroll
    for (int mt = 0; mt < 4; mt++) {
        int row = bm0 + wm + mt * 16 + lr;
#pragma unroll
        for (int nt = 0; nt < 4; nt++) {
            int col = bn0 + wn + nt * 8 + lc * 2;
            *(float2*)&C[(size_t)row * N + col]       = make_float2(acc[mt][nt][0], acc[mt][nt][1]);
            *(float2*)&C[(size_t)(row + 8) * N + col] = make_float2(acc[mt][nt][2], acc[mt][nt][3]);
        }
    }
}

// ---------------------------------------------------------------------------
// RoPE (in place)
// ---------------------------------------------------------------------------
__global__ __launch_bounds__(256) void rope_q_kernel()
{
    int idx = blockIdx.x * 256 + threadIdx.x;
    int j = idx & 63;
    int h = (idx >> 6) & (H_ - 1);
    int t = (idx >> 10) & (T_ - 1);
    int b = idx >> 21;
    float inv = powf(10000.0f, -(float)j * (1.0f / 64.0f));
    float ang = (float)t * inv;
    float sv, cv;
    sincosf(ang, &sv, &cv);
    size_t base = (((size_t)b * T_ + t) * H_ + h) * (size_t)HD_;
    float x1 = g_q[base + j], x2 = g_q[base + j + 64];
    g_q[base + j]      = x1 * cv - x2 * sv;
    g_q[base + j + 64] = x2 * cv + x1 * sv;
}

__global__ __launch_bounds__(256) void rope_k_kernel(float* __restrict__ kb)
{
    int idx = blockIdx.x * 256 + threadIdx.x;
    int j = idx & 63;
    int t = (idx >> 6) & (T_ - 1);
    int b = idx >> 17;
    float inv = powf(10000.0f, -(float)j * (1.0f / 64.0f));
    float ang = (float)t * inv;
    float sv, cv;
    sincosf(ang, &sv, &cv);
    size_t base = ((size_t)b * T_ + t) * (size_t)HD_;
    float x1 = kb[base + j], x2 = kb[base + j + 64];
    kb[base + j]      = x1 * cv - x2 * sv;
    kb[base + j + 64] = x2 * cv + x1 * sv;
}

// ---------------------------------------------------------------------------
// Tensor-core flash attention, bf16x3 split precision.
// BQ=128, BKV=64, 256 threads (8 warps). Warp w owns S/O rows w*16..w*16+15.
// Softmax state in registers (4-lane groups + shfl).
// ---------------------------------------------------------------------------
#define BQ 128
#define BKV 64
#define QSTR 136    // bf16 row stride for Q/K tiles (68 words -> conflict-free frags)
#define VSTR 72     // bf16 row stride for V^T / P tiles (36 words)

__global__ __launch_bounds__(256) void flash_attn_tc(
    const float* __restrict__ kbuf, const float* __restrict__ vbuf)
{
    extern __shared__ char smc[];
    __nv_bfloat16* Qh = (__nv_bfloat16*)smc;          // [BQ][QSTR]
    __nv_bfloat16* Ql = Qh + BQ * QSTR;
    __nv_bfloat16* Kh = Ql + BQ * QSTR;               // [BKV][QSTR]
    __nv_bfloat16* Kl = Kh + BKV * QSTR;
    __nv_bfloat16* Vh = Kl + BKV * QSTR;              // [HD][VSTR]  (V^T: [d][kv])
    __nv_bfloat16* Vl = Vh + HD_ * VSTR;
    __nv_bfloat16* Ph = Vl + HD_ * VSTR;              // [BQ][VSTR]
    __nv_bfloat16* Pl = Ph + BQ * VSTR;

    int tid = threadIdx.x;
    int w = tid >> 5, lane = tid & 31;
    int lr = lane >> 2, lc = lane & 3;
    int qb = blockIdx.x;
    int bh = (int)blockIdx.y;
    int b = bh >> 4, h = bh & 15;
    int q0 = qb * BQ;
    int rb = w * 16;
    const float scale = 0.08838834764831845f;   // 1/sqrt(128)

    // ---- Load Q tile (scale folded, hi/lo split) ----
    {
        const float* qp = g_q + (((size_t)b * T_ + q0) * H_ + h) * (size_t)HD_;
#pragma unroll
        for (int it = 0; it < 16; it++) {
            int i = tid + it * 256;              // 128 rows x 32 float4
            int r = i >> 5, d4 = (i & 31) << 2;
            float4 v = *(const float4*)(qp + (size_t)r * DIM_ + d4);
            float vv[4] = {v.x * scale, v.y * scale, v.z * scale, v.w * scale};
            __nv_bfloat16 hh[4], ll[4];
#pragma unroll
            for (int j = 0; j < 4; j++) {
                hh[j] = __float2bfloat16(vv[j]);
                ll[j] = __float2bfloat16(vv[j] - __bfloat162float(hh[j]));
            }
            *(uint32_t*)&Qh[r * QSTR + d4]     = *(uint32_t*)&hh[0];
            *(uint32_t*)&Qh[r * QSTR + d4 + 2] = *(uint32_t*)&hh[2];
            *(uint32_t*)&Ql[r * QSTR + d4]     = *(uint32_t*)&ll[0];
            *(uint32_t*)&Ql[r * QSTR + d4 + 2] = *(uint32_t*)&ll[2];
        }
    }

    // per-thread softmax state: rows rb+lr and rb+lr+8 (replicated over 4 lanes)
    float m0r = -1e30f, m1r = -1e30f, l0r = 0.f, l1r = 0.f;
    float O[16][4];
#pragma unroll
    for (int i = 0; i < 16; i++)
#pragma unroll
        for (int j = 0; j < 4; j++) O[i][j] = 0.f;

    const float* kb_base = kbuf + (size_t)b * T_ * HD_;
    const float* vb_base = vbuf + (size_t)b * T_ * HD_;
    int ntiles = 2 * qb + 2;

    for (int kt = 0; kt < ntiles; kt++) {
        int k0 = kt * BKV;
        __syncthreads();   // previous PV reads of Vs done; Q stores ordered (first iter)

        // ---- Load K tile (split) ----
#pragma unroll
        for (int it = 0; it < 8; it++) {
            int i = tid + it * 256;              // 64 rows x 32 float4
            int r = i >> 5, d4 = (i & 31) << 2;
            float4 v = *(const float4*)(kb_base + (size_t)(k0 + r) * HD_ + d4);
            float vv[4] = {v.x, v.y, v.z, v.w};
            __nv_bfloat16 hh[4], ll[4];
#pragma unroll
            for (int j = 0; j < 4; j++) {
                hh[j] = __float2bfloat16(vv[j]);
                ll[j] = __float2bfloat16(vv[j] - __bfloat162float(hh[j]));
            }
            *(uint32_t*)&Kh[r * QSTR + d4]     = *(uint32_t*)&hh[0];
            *(uint32_t*)&Kh[r * QSTR + d4 + 2] = *(uint32_t*)&hh[2];
            *(uint32_t*)&Kl[r * QSTR + d4]     = *(uint32_t*)&ll[0];
            *(uint32_t*)&Kl[r * QSTR + d4 + 2] = *(uint32_t*)&ll[2];
            // ---- V tile: transpose + split ----
            float4 u = *(const float4*)(vb_base + (size_t)(k0 + r) * HD_ + d4);
            float uu[4] = {u.x, u.y, u.z, u.w};
#pragma unroll
            for (int j = 0; j < 4; j++) {
                __nv_bfloat16 vh = __float2bfloat16(uu[j]);
                __nv_bfloat16 vl = __float2bfloat16(uu[j] - __bfloat162float(vh));
                Vh[(d4 + j) * VSTR + r] = vh;
                Vl[(d4 + j) * VSTR + r] = vl;
            }
        }
        __syncthreads();

        // ---- S = Q @ K^T (bf16x3), warp rows rb..rb+15, cols 0..63 ----
        float sacc[8][4];
#pragma unroll
        for (int nt = 0; nt < 8; nt++)
#pragma unroll
            for (int j = 0; j < 4; j++) sacc[nt][j] = 0.f;

#pragma unroll
        for (int kk = 0; kk < 8; kk++) {
            int ke = kk * 16;
            uint32_t ah0 = *(uint32_t*)&Qh[(rb + lr) * QSTR + ke + 2 * lc];
            uint32_t ah1 = *(uint32_t*)&Qh[(rb + lr + 8) * QSTR + ke + 2 * lc];
            uint32_t ah2 = *(uint32_t*)&Qh[(rb + lr) * QSTR + ke + 2 * lc + 8];
            uint32_t ah3 = *(uint32_t*)&Qh[(rb + lr + 8) * QSTR + ke + 2 * lc + 8];
            uint32_t al0 = *(uint32_t*)&Ql[(rb + lr) * QSTR + ke + 2 * lc];
            uint32_t al1 = *(uint32_t*)&Ql[(rb + lr + 8) * QSTR + ke + 2 * lc];
            uint32_t al2 = *(uint32_t*)&Ql[(rb + lr) * QSTR + ke + 2 * lc + 8];
            uint32_t al3 = *(uint32_t*)&Ql[(rb + lr + 8) * QSTR + ke + 2 * lc + 8];
#pragma unroll
            for (int nt = 0; nt < 8; nt++) {
                int n = nt * 8 + lr;
                uint32_t bh0 = *(uint32_t*)&Kh[n * QSTR + ke + 2 * lc];
                uint32_t bh1 = *(uint32_t*)&Kh[n * QSTR + ke + 2 * lc + 8];
                uint32_t bl0 = *(uint32_t*)&Kl[n * QSTR + ke + 2 * lc];
                uint32_t bl1 = *(uint32_t*)&Kl[n * QSTR + ke + 2 * lc + 8];
                mmabf(sacc[nt], ah0, ah1, ah2, ah3, bh0, bh1);
                mmabf(sacc[nt], ah0, ah1, ah2, ah3, bl0, bl1);
                mmabf(sacc[nt], al0, al1, al2, al3, bh0, bh1);
            }
        }

        // ---- causal mask (only last two tiles can touch the diagonal) ----
        if (k0 + BKV > q0) {
            int r0g = q0 + rb + lr, r1g = r0g + 8;
#pragma unroll
            for (int nt = 0; nt < 8; nt++) {
                int cg = k0 + nt * 8 + 2 * lc;
                if (cg > r0g)     sacc[nt][0] = -1e30f;
                if (cg + 1 > r0g) sacc[nt][1] = -1e30f;
                if (cg > r1g)     sacc[nt][2] = -1e30f;
                if (cg + 1 > r1g) sacc[nt][3] = -1e30f;
            }
        }

        // ---- online softmax (register state, 4-lane shfl reduce) ----
        float mt0 = -1e30f, mt1 = -1e30f;
#pragma unroll
        for (int nt = 0; nt < 8; nt++) {
            mt0 = fmaxf(mt0, fmaxf(sacc[nt][0], sacc[nt][1]));
            mt1 = fmaxf(mt1, fmaxf(sacc[nt][2], sacc[nt][3]));
        }
        mt0 = fmaxf(mt0, __shfl_xor_sync(0xffffffff, mt0, 1));
        mt0 = fmaxf(mt0, __shfl_xor_sync(0xffffffff, mt0, 2));
        mt1 = fmaxf(mt1, __shfl_xor_sync(0xffffffff, mt1, 1));
        mt1 = fmaxf(mt1, __shfl_xor_sync(0xffffffff, mt1, 2));

        float mn0 = fmaxf(m0r, mt0), mn1 = fmaxf(m1r, mt1);
        float al0f = __expf(m0r - mn0), al1f = __expf(m1r - mn1);
        m0r = mn0; m1r = mn1;

        float rs0 = 0.f, rs1 = 0.f;
#pragma unroll
        for (int nt = 0; nt < 8; nt++) {
            float p0 = __expf(sacc[nt][0] - mn0);
            float p1 = __expf(sacc[nt][1] - mn0);
            float p2 = __expf(sacc[nt][2] - mn1);
            float p3 = __expf(sacc[nt][3] - mn1);
            rs0 += p0 + p1; rs1 += p2 + p3;
            // split P to hi/lo bf16, store packed pairs
            uint32_t h01 = pack_hi(p0, p1);
            uint32_t h23 = pack_hi(p2, p3);
            __nv_bfloat162 hb = *(__nv_bfloat162*)&h01;
            __nv_bfloat162 hb2 = *(__nv_bfloat162*)&h23;
            uint32_t l01 = pack_hi(p0 - __bfloat162float(hb.x), p1 - __bfloat162float(hb.y));
            uint32_t l23 = pack_hi(p2 - __bfloat162float(hb2.x), p3 - __bfloat162float(hb2.y));
            *(uint32_t*)&Ph[(rb + lr) * VSTR + nt * 8 + 2 * lc]     = h01;
            *(uint32_t*)&Ph[(rb + lr + 8) * VSTR + nt * 8 + 2 * lc] = h23;
            *(uint32_t*)&Pl[(rb + lr) * VSTR + nt * 8 + 2 * lc]     = l01;
            *(uint32_t*)&Pl[(rb + lr + 8) * VSTR + nt * 8 + 2 * lc] = l23;
        }
        rs0 += __shfl_xor_sync(0xffffffff, rs0, 1);
        rs0 += __shfl_xor_sync(0xffffffff, rs0, 2);
        rs1 += __shfl_xor_sync(0xffffffff, rs1, 1);
        rs1 += __shfl_xor_sync(0xffffffff, rs1, 2);
        l0r = l0r * al0f + rs0;
        l1r = l1r * al1f + rs1;

        // rescale O
#pragma unroll
        for (int nt = 0; nt < 16; nt++) {
            O[nt][0] *= al0f; O[nt][1] *= al0f;
            O[nt][2] *= al1f; O[nt][3] *= al1f;
        }
        __syncwarp();   // P visible to all lanes of this warp (rows are warp-private)

        // ---- O += P @ V (bf16x3), cols = 16 ntiles of 8 over d ----
#pragma unroll
        for (int kk = 0; kk < 4; kk++) {
            int ke = kk * 16;
            uint32_t ah0 = *(uint32_t*)&Ph[(rb + lr) * VSTR + ke + 2 * lc];
            uint32_t ah1 = *(uint32_t*)&Ph[(rb + lr + 8) * VSTR + ke + 2 * lc];
            uint32_t ah2 = *(uint32_t*)&Ph[(rb + lr) * VSTR + ke + 2 * lc + 8];
            uint32_t ah3 = *(uint32_t*)&Ph[(rb + lr + 8) * VSTR + ke + 2 * lc + 8];
            uint32_t al0 = *(uint32_t*)&Pl[(rb + lr) * VSTR + ke + 2 * lc];
            uint32_t al1 = *(uint32_t*)&Pl[(rb + lr + 8) * VSTR + ke + 2 * lc];
            uint32_t al2 = *(uint32_t*)&Pl[(rb + lr) * VSTR + ke + 2 * lc + 8];
            uint32_t al3 = *(uint32_t*)&Pl[(rb + lr + 8) * VSTR + ke + 2 * lc + 8];
#pragma unroll
            for (int nt = 0; nt < 16; nt++) {
                int n = nt * 8 + lr;
                uint32_t bh0 = *(uint32_t*)&Vh[n * VSTR + ke + 2 * lc];
                uint32_t bh1 = *(uint32_t*)&Vh[n * VSTR + ke + 2 * lc + 8];
                uint32_t bl0 = *(uint32_t*)&Vl[n * VSTR + ke + 2 * lc];
                uint32_t bl1 = *(uint32_t*)&Vl[n * VSTR + ke + 2 * lc + 8];
                mmabf(O[nt], ah0, ah1, ah2, ah3, bh0, bh1);
                mmabf(O[nt], ah0, ah1, ah2, ah3, bl0, bl1);
                mmabf(O[nt], al0, al1, al2, al3, bh0, bh1);
            }
        }
    }

    // ---- finalize: O / l -> g_attn [B,T,H,HD] ----
    float inv0 = 1.f / l0r, inv1 = 1.f / l1r;
    float* ob = g_attn + (((size_t)b * T_ + q0) * H_ + h) * (size_t)HD_;
#pragma unroll
    for (int nt = 0; nt < 16; nt++) {
        int col = nt * 8 + 2 * lc;
        *(float2*)&ob[(size_t)(rb + lr) * DIM_ + col] =
            make_float2(O[nt][0] * inv0, O[nt][1] * inv0);
        *(float2*)&ob[(size_t)(rb + lr + 8) * DIM_ + col] =
            make_float2(O[nt][2] * inv1, O[nt][3] * inv1);
    }
}

static const int FLASH_SMEM =
    (2 * BQ * QSTR + 2 * BKV * QSTR + 2 * HD_ * VSTR + 2 * BQ * VSTR) * 2;

// ---------------------------------------------------------------------------
extern "C" void kernel_launch(void* const* d_in, const int* in_sizes, int n_in,
                              void* d_out, int out_size)
{
    const float* x  = (const float*)d_in[0];
    const float* Wq = (const float*)d_in[1];
    const float* Wk = (const float*)d_in[2];
    const float* Wv = (const float*)d_in[3];
    const float* Wo = (const float*)d_in[4];

    float* out = (float*)d_out;                       // [B,T,DIM]
    float* pk  = out + (size_t)BT_ * DIM_;            // present_k [B,1,T,HD]
    float* pv  = pk + (size_t)BT_ * HD_;              // present_v [B,1,T,HD]

    cudaFuncSetAttribute(flash_attn_tc, cudaFuncAttributeMaxDynamicSharedMemorySize, FLASH_SMEM);

    dim3 blk(256);
    tgemm<<<dim3(DIM_ / 128, BT_ / 128), blk>>>(x, Wq, nullptr, BT_, DIM_, DIM_, 0, 1);
    tgemm<<<dim3(1, BT_ / 128), blk>>>(x, Wk, pk, BT_, HD_, DIM_, 0, 0);
    tgemm<<<dim3(1, BT_ / 128), blk>>>(x, Wv, pv, BT_, HD_, DIM_, 0, 0);

    rope_q_kernel<<<(BT_ * H_ * 64) / 256, blk>>>();
    rope_k_kernel<<<(BT_ * 64) / 256, blk>>>(pk);

    flash_attn_tc<<<dim3(T_ / BQ, B_ * H_), blk, FLASH_SMEM>>>(pk, pv);

    tgemm<<<dim3(DIM_ / 128, BT_ / 128), blk>>>(nullptr, Wo, out, BT_, DIM_, DIM_, 1, 0);
}

// round 6
// speedup vs baseline: 1.0886x; 1.0886x over previous
#include <cuda_runtime.h>
#include <cuda_bf16.h>
#include <math.h>
#include <stdint.h>

#define B_ 2
#define T_ 2048
#define DIM_ 2048
#define H_ 16
#define HD_ 128
#define BT_ (B_ * T_)

// Scratch (alloc-free rules: __device__ globals)
static __device__ float g_q[(size_t)BT_ * DIM_];     // Q after GEMM+RoPE, [B,T,H,HD]
static __device__ float g_attn[(size_t)BT_ * DIM_];  // attention out, [B,T,DIM]

// ---------------------------------------------------------------------------
// TF32 helpers
// ---------------------------------------------------------------------------
__device__ __forceinline__ uint32_t f2tf(float x) {
    uint32_t r;
    asm("cvt.rna.tf32.f32 %0, %1;" : "=r"(r) : "f"(x));
    return r;
}

__device__ __forceinline__ void mma8(float* c, uint32_t a0, uint32_t a1, uint32_t a2,
                                     uint32_t a3, uint32_t b0, uint32_t b1) {
    asm volatile(
        "mma.sync.aligned.m16n8k8.row.col.f32.tf32.tf32.f32 "
        "{%0,%1,%2,%3},{%4,%5,%6,%7},{%8,%9},{%0,%1,%2,%3};"
        : "+f"(c[0]), "+f"(c[1]), "+f"(c[2]), "+f"(c[3])
        : "r"(a0), "r"(a1), "r"(a2), "r"(a3), "r"(b0), "r"(b1));
}

// ---------------------------------------------------------------------------
// TF32 tensor-core GEMM, double-buffered + software-pipelined.
// C[M,N] = A[M,K] @ B[K,N]. 128x128 tile, BK=16, 256 thr (8 warps 2x4, 64x32).
// blockIdx.z selects (B0,C0) vs (B1,C1) for fused K/V. asel/csel pick scratch.
// ---------------------------------------------------------------------------
__global__ __launch_bounds__(256, 2) void tgemm(
    const float* __restrict__ A,
    const float* __restrict__ B0, const float* __restrict__ B1,
    float* __restrict__ C0, float* __restrict__ C1,
    int M, int N, int K, int asel, int csel)
{
    const float* Bm = blockIdx.z ? B1 : B0;
    float* C = blockIdx.z ? C1 : C0;
    if (asel == 1) A = g_attn;
    if (csel == 1) C = g_q;

    __shared__ uint32_t As[2][16][136];   // [stage][k][m]
    __shared__ uint32_t Bs[2][16][136];   // [stage][k][n]

    int tid = threadIdx.x;
    int bn0 = blockIdx.x * 128, bm0 = blockIdx.y * 128;
    int warp = tid >> 5, lane = tid & 31;
    int wm = (warp & 1) * 64, wn = (warp >> 1) * 32;
    int lr = lane >> 2, lc = lane & 3;

    float acc[4][4][4];
#pragma unroll
    for (int mt = 0; mt < 4; mt++)
#pragma unroll
        for (int nt = 0; nt < 4; nt++)
#pragma unroll
            for (int i = 0; i < 4; i++) acc[mt][nt][i] = 0.f;

    int ar = tid >> 2, ac = (tid & 3) << 2;     // A: rows ar, ar+64; k cols ac..ac+3
    int br = tid >> 5, bc = (tid & 31) << 2;    // B: k rows br, br+8; n cols bc..bc+3

    const float* Ap = A + (size_t)(bm0 + ar) * K + ac;
    const float* Bp = Bm + (size_t)br * N + bn0 + bc;

    // ---- prologue: tile 0 -> stage 0 ----
    {
        float4 a0v = *(const float4*)(Ap);
        float4 a1v = *(const float4*)(Ap + (size_t)64 * K);
        float4 b0v = *(const float4*)(Bp);
        float4 b1v = *(const float4*)(Bp + (size_t)8 * N);
        As[0][ac + 0][ar] = f2tf(a0v.x); As[0][ac + 1][ar] = f2tf(a0v.y);
        As[0][ac + 2][ar] = f2tf(a0v.z); As[0][ac + 3][ar] = f2tf(a0v.w);
        As[0][ac + 0][ar + 64] = f2tf(a1v.x); As[0][ac + 1][ar + 64] = f2tf(a1v.y);
        As[0][ac + 2][ar + 64] = f2tf(a1v.z); As[0][ac + 3][ar + 64] = f2tf(a1v.w);
        *(uint4*)&Bs[0][br][bc]     = make_uint4(f2tf(b0v.x), f2tf(b0v.y), f2tf(b0v.z), f2tf(b0v.w));
        *(uint4*)&Bs[0][br + 8][bc] = make_uint4(f2tf(b1v.x), f2tf(b1v.y), f2tf(b1v.z), f2tf(b1v.w));
    }
    __syncthreads();

    int nk = K >> 4;
    int p = 0;
    for (int t = 0; t < nk; t++) {
        // ---- prefetch tile t+1 (LDG latency hidden by the compute below) ----
        float4 na0, na1, nb0, nb1;
        bool more = (t + 1 < nk);
        if (more) {
            Ap += 16;
            Bp += (size_t)16 * N;
            na0 = *(const float4*)(Ap);
            na1 = *(const float4*)(Ap + (size_t)64 * K);
            nb0 = *(const float4*)(Bp);
            nb1 = *(const float4*)(Bp + (size_t)8 * N);
        }

        // ---- compute from stage p ----
#pragma unroll
        for (int kk = 0; kk < 16; kk += 8) {
            uint32_t bf[4][2];
#pragma unroll
            for (int nt = 0; nt < 4; nt++) {
                bf[nt][0] = Bs[p][kk + lc][wn + nt * 8 + lr];
                bf[nt][1] = Bs[p][kk + lc + 4][wn + nt * 8 + lr];
            }
#pragma unroll
            for (int mt = 0; mt < 4; mt++) {
                uint32_t a0 = As[p][kk + lc][wm + mt * 16 + lr];
                uint32_t a1 = As[p][kk + lc][wm + mt * 16 + lr + 8];
                uint32_t a2 = As[p][kk + lc + 4][wm + mt * 16 + lr];
                uint32_t a3 = As[p][kk + lc + 4][wm + mt * 16 + lr + 8];
#pragma unroll
                for (int nt = 0; nt < 4; nt++)
                    mma8(acc[mt][nt], a0, a1, a2, a3, bf[nt][0], bf[nt][1]);
            }
        }

        // ---- stage flip: store prefetched tile into the other buffer ----
        if (more) {
            int q = p ^ 1;
            __syncthreads();   // (needed only to order reuse of buffer q from t-1)
            As[q][ac + 0][ar] = f2tf(na0.x); As[q][ac + 1][ar] = f2tf(na0.y);
            As[q][ac + 2][ar] = f2tf(na0.z); As[q][ac + 3][ar] = f2tf(na0.w);
            As[q][ac + 0][ar + 64] = f2tf(na1.x); As[q][ac + 1][ar + 64] = f2tf(na1.y);
            As[q][ac + 2][ar + 64] = f2tf(na1.z); As[q][ac + 3][ar + 64] = f2tf(na1.w);
            *(uint4*)&Bs[q][br][bc]     = make_uint4(f2tf(nb0.x), f2tf(nb0.y), f2tf(nb0.z), f2tf(nb0.w));
            *(uint4*)&Bs[q][br + 8][bc] = make_uint4(f2tf(nb1.x), f2tf(nb1.y), f2tf(nb1.z), f2tf(nb1.w));
            __syncthreads();
            p = q;
        }
    }

#pragma unroll
    for (int mt = 0; mt < 4; mt++) {
        int row = bm0 + wm + mt * 16 + lr;
#pragma unroll
        for (int nt = 0; nt < 4; nt++) {
            int col = bn0 + wn + nt * 8 + lc * 2;
            *(float2*)&C[(size_t)row * N + col]       = make_float2(acc[mt][nt][0], acc[mt][nt][1]);
            *(float2*)&C[(size_t)(row + 8) * N + col] = make_float2(acc[mt][nt][2], acc[mt][nt][3]);
        }
    }
}

// ---------------------------------------------------------------------------
// RoPE (in place)
// ---------------------------------------------------------------------------
__global__ __launch_bounds__(256) void rope_q_kernel()
{
    int idx = blockIdx.x * 256 + threadIdx.x;      // < B*T*H*64
    int j = idx & 63;
    int h = (idx >> 6) & (H_ - 1);
    int t = (idx >> 10) & (T_ - 1);
    int b = idx >> 21;
    float inv = powf(10000.0f, -(float)j * (1.0f / 64.0f));
    float ang = (float)t * inv;
    float sv, cv;
    sincosf(ang, &sv, &cv);
    size_t base = (((size_t)b * T_ + t) * H_ + h) * (size_t)HD_;
    float x1 = g_q[base + j], x2 = g_q[base + j + 64];
    g_q[base + j]      = x1 * cv - x2 * sv;
    g_q[base + j + 64] = x2 * cv + x1 * sv;
}

__global__ __launch_bounds__(256) void rope_k_kernel(float* __restrict__ kb)
{
    int idx = blockIdx.x * 256 + threadIdx.x;      // < B*T*64
    int j = idx & 63;
    int t = (idx >> 6) & (T_ - 1);
    int b = idx >> 17;
    float inv = powf(10000.0f, -(float)j * (1.0f / 64.0f));
    float ang = (float)t * inv;
    float sv, cv;
    sincosf(ang, &sv, &cv);
    size_t base = ((size_t)b * T_ + t) * (size_t)HD_;
    float x1 = kb[base + j], x2 = kb[base + j + 64];
    kb[base + j]      = x1 * cv - x2 * sv;
    kb[base + j + 64] = x2 * cv + x1 * sv;
}

// ---------------------------------------------------------------------------
// Flash attention, fp32, BQ=BKV=64 (proven R2 version)
// ---------------------------------------------------------------------------
#define BQ 64
#define BKV 64
#define TSTR 68
#define PSTR 68
#define MSTR 17

__global__ __launch_bounds__(256) void flash_attn(
    const float* __restrict__ kbuf, const float* __restrict__ vbuf)
{
    extern __shared__ float sm[];
    float* Qs   = sm;                    // [HD][TSTR]
    float* Ks   = Qs + HD_ * TSTR;       // [HD][TSTR]
    float* Vs   = Ks + HD_ * TSTR;       // [BKV][HD]
    float* Ps   = Vs + BKV * HD_;        // [BQ][PSTR]
    float* pmax = Ps + BQ * PSTR;        // [BQ][MSTR]
    float* psum = pmax + BQ * MSTR;      // [BQ][MSTR]
    float* rowm = psum + BQ * MSTR;      // [BQ]
    float* rowl = rowm + BQ;
    float* rowa = rowl + BQ;

    int tid = threadIdx.x;
    int tx = tid & 15, ty = tid >> 4;
    int qb = blockIdx.x;
    int bh = (int)blockIdx.y;
    int b = bh >> 4, h = bh & 15;
    int q0 = qb * BQ;
    const float scale = 0.08838834764831845f;

    if (tid < BQ) { rowm[tid] = -INFINITY; rowl[tid] = 0.f; }

    {
        int r = tid >> 5;
        int d4 = (tid & 31) << 2;
        const float* qp = g_q + (((size_t)b * T_ + q0) * H_ + h) * (size_t)HD_;
#pragma unroll
        for (int it = 0; it < 8; it++, r += 8) {
            float4 v = *(const float4*)(qp + (size_t)r * DIM_ + d4);
            float vv[4] = {v.x * scale, v.y * scale, v.z * scale, v.w * scale};
#pragma unroll
            for (int cc = 0; cc < 4; cc++) {
                int c = (cc + tid) & 3;
                Qs[(d4 + c) * TSTR + r] = vv[c];
            }
        }
    }

    float O[4][8];
#pragma unroll
    for (int i = 0; i < 4; i++)
#pragma unroll
        for (int j = 0; j < 8; j++) O[i][j] = 0.f;

    const float* kb_base = kbuf + (size_t)b * T_ * HD_;
    const float* vb_base = vbuf + (size_t)b * T_ * HD_;

    for (int kb = 0; kb <= qb; kb++) {
        int k0 = kb * BKV;
        __syncthreads();
        {
            int r = tid >> 5;
            int d4 = (tid & 31) << 2;
#pragma unroll
            for (int it = 0; it < 8; it++, r += 8) {
                float4 kv = *(const float4*)(kb_base + (size_t)(k0 + r) * HD_ + d4);
                float kk[4] = {kv.x, kv.y, kv.z, kv.w};
#pragma unroll
                for (int cc = 0; cc < 4; cc++) {
                    int c = (cc + tid) & 3;
                    Ks[(d4 + c) * TSTR + r] = kk[c];
                }
                float4 vv = *(const float4*)(vb_base + (size_t)(k0 + r) * HD_ + d4);
                *(float4*)&Vs[r * HD_ + d4] = vv;
            }
        }
        __syncthreads();

        float s[4][4];
#pragma unroll
        for (int i = 0; i < 4; i++)
#pragma unroll
            for (int j = 0; j < 4; j++) s[i][j] = 0.f;

#pragma unroll 4
        for (int d = 0; d < HD_; d++) {
            float4 a  = *(const float4*)&Qs[d * TSTR + ty * 4];
            float4 bb = *(const float4*)&Ks[d * TSTR + tx * 4];
            float av[4] = {a.x, a.y, a.z, a.w};
            float bv[4] = {bb.x, bb.y, bb.z, bb.w};
#pragma unroll
            for (int i = 0; i < 4; i++)
#pragma unroll
                for (int j = 0; j < 4; j++)
                    s[i][j] = fmaf(av[i], bv[j], s[i][j]);
        }

        if (kb == qb) {
#pragma unroll
            for (int i = 0; i < 4; i++)
#pragma unroll
                for (int j = 0; j < 4; j++)
                    if (ty * 4 + i < tx * 4 + j) s[i][j] = -1e30f;
        }

#pragma unroll
        for (int i = 0; i < 4; i++) {
            float mx = fmaxf(fmaxf(s[i][0], s[i][1]), fmaxf(s[i][2], s[i][3]));
            pmax[(ty * 4 + i) * MSTR + tx] = mx;
        }
        __syncthreads();

        if (tid < BQ) {
            float mt = -INFINITY;
#pragma unroll
            for (int t = 0; t < 16; t++) mt = fmaxf(mt, pmax[tid * MSTR + t]);
            float mo = rowm[tid];
            float mn = fmaxf(mo, mt);
            rowm[tid] = mn;
            rowa[tid] = __expf(mo - mn);
        }
        __syncthreads();

#pragma unroll
        for (int i = 0; i < 4; i++) {
            float mn = rowm[ty * 4 + i];
            float p0 = __expf(s[i][0] - mn);
            float p1 = __expf(s[i][1] - mn);
            float p2 = __expf(s[i][2] - mn);
            float p3 = __expf(s[i][3] - mn);
            *(float4*)&Ps[(ty * 4 + i) * PSTR + tx * 4] = make_float4(p0, p1, p2, p3);
            psum[(ty * 4 + i) * MSTR + tx] = p0 + p1 + p2 + p3;
        }
        __syncthreads();

        if (tid < BQ) {
            float sum = 0.f;
#pragma unroll
            for (int t = 0; t < 16; t++) sum += psum[tid * MSTR + t];
            rowl[tid] = rowl[tid] * rowa[tid] + sum;
        }

#pragma unroll
        for (int i = 0; i < 4; i++) {
            float al = rowa[ty * 4 + i];
#pragma unroll
            for (int j = 0; j < 8; j++) O[i][j] *= al;
        }
#pragma unroll 2
        for (int k = 0; k < BKV; k++) {
            float p[4];
#pragma unroll
            for (int i = 0; i < 4; i++) p[i] = Ps[(ty * 4 + i) * PSTR + k];
            float4 v0 = *(const float4*)&Vs[k * HD_ + tx * 8];
            float4 v1 = *(const float4*)&Vs[k * HD_ + tx * 8 + 4];
            float vv[8] = {v0.x, v0.y, v0.z, v0.w, v1.x, v1.y, v1.z, v1.w};
#pragma unroll
            for (int i = 0; i < 4; i++)
#pragma unroll
                for (int j = 0; j < 8; j++)
                    O[i][j] = fmaf(p[i], vv[j], O[i][j]);
        }
    }
    __syncthreads();

#pragma unroll
    for (int i = 0; i < 4; i++) {
        float inv = 1.f / rowl[ty * 4 + i];
        float* op = g_attn + (((size_t)b * T_ + q0 + ty * 4 + i) * H_ + h) * (size_t)HD_ + tx * 8;
        *(float4*)op       = make_float4(O[i][0] * inv, O[i][1] * inv, O[i][2] * inv, O[i][3] * inv);
        *(float4*)(op + 4) = make_float4(O[i][4] * inv, O[i][5] * inv, O[i][6] * inv, O[i][7] * inv);
    }
}

static const int FLASH_SMEM = (HD_ * TSTR * 2 + BKV * HD_ + BQ * PSTR + BQ * MSTR * 2 + 3 * BQ) * 4;

// ---------------------------------------------------------------------------
extern "C" void kernel_launch(void* const* d_in, const int* in_sizes, int n_in,
                              void* d_out, int out_size)
{
    const float* x  = (const float*)d_in[0];
    const float* Wq = (const float*)d_in[1];
    const float* Wk = (const float*)d_in[2];
    const float* Wv = (const float*)d_in[3];
    const float* Wo = (const float*)d_in[4];

    float* out = (float*)d_out;                       // [B,T,DIM]
    float* pk  = out + (size_t)BT_ * DIM_;            // present_k [B,1,T,HD]
    float* pv  = pk + (size_t)BT_ * HD_;              // present_v [B,1,T,HD]

    cudaFuncSetAttribute(flash_attn, cudaFuncAttributeMaxDynamicSharedMemorySize, FLASH_SMEM);

    dim3 blk(256);
    // Q = x @ Wq  -> g_q
    tgemm<<<dim3(DIM_ / 128, BT_ / 128, 1), blk>>>(x, Wq, Wq, nullptr, nullptr,
                                                   BT_, DIM_, DIM_, 0, 1);
    // K,V fused via blockIdx.z: z=0 -> (Wk, pk), z=1 -> (Wv, pv)
    tgemm<<<dim3(1, BT_ / 128, 2), blk>>>(x, Wk, Wv, pk, pv, BT_, HD_, DIM_, 0, 0);

    rope_q_kernel<<<(BT_ * H_ * 64) / 256, blk>>>();
    rope_k_kernel<<<(BT_ * 64) / 256, blk>>>(pk);

    flash_attn<<<dim3(T_ / BQ, B_ * H_), blk, FLASH_SMEM>>>(pk, pv);

    // out = attn @ Wo
    tgemm<<<dim3(DIM_ / 128, BT_ / 128, 1), blk>>>(nullptr, Wo, Wo, out, out,
                                                   BT_, DIM_, DIM_, 1, 0);
}

// round 7
// speedup vs baseline: 2.1626x; 1.9866x over previous
#include <cuda_runtime.h>
#include <cuda_bf16.h>
#include <math.h>
#include <stdint.h>

#define B_ 2
#define T_ 2048
#define DIM_ 2048
#define H_ 16
#define HD_ 128
#define BT_ (B_ * T_)

// ---------------------------------------------------------------------------
// Scratch (alloc-free rules: __device__ globals)
// ---------------------------------------------------------------------------
static __device__ float g_q[(size_t)BT_ * DIM_];     // Q after GEMM (pre-RoPE), [B,T,H,HD]
static __device__ float g_attn[(size_t)BT_ * DIM_];  // attention out, [B,T,DIM]
static __device__ __nv_bfloat16 g_qh[(size_t)BT_ * DIM_];   // roped+scaled Q hi/lo
static __device__ __nv_bfloat16 g_ql[(size_t)BT_ * DIM_];
static __device__ __nv_bfloat16 g_kh[(size_t)BT_ * HD_];    // roped K hi/lo [B,T,HD]
static __device__ __nv_bfloat16 g_kl[(size_t)BT_ * HD_];
static __device__ __nv_bfloat16 g_vth[(size_t)BT_ * HD_];   // V^T hi/lo [B,HD,T]
static __device__ __nv_bfloat16 g_vtl[(size_t)BT_ * HD_];

// ---------------------------------------------------------------------------
// mma helpers
// ---------------------------------------------------------------------------
__device__ __forceinline__ uint32_t f2tf(float x) {
    uint32_t r;
    asm("cvt.rna.tf32.f32 %0, %1;" : "=r"(r) : "f"(x));
    return r;
}

__device__ __forceinline__ void mma8(float* c, uint32_t a0, uint32_t a1, uint32_t a2,
                                     uint32_t a3, uint32_t b0, uint32_t b1) {
    asm volatile(
        "mma.sync.aligned.m16n8k8.row.col.f32.tf32.tf32.f32 "
        "{%0,%1,%2,%3},{%4,%5,%6,%7},{%8,%9},{%0,%1,%2,%3};"
        : "+f"(c[0]), "+f"(c[1]), "+f"(c[2]), "+f"(c[3])
        : "r"(a0), "r"(a1), "r"(a2), "r"(a3), "r"(b0), "r"(b1));
}

__device__ __forceinline__ void mmabf(float* c, uint32_t a0, uint32_t a1, uint32_t a2,
                                      uint32_t a3, uint32_t b0, uint32_t b1) {
    asm volatile(
        "mma.sync.aligned.m16n8k16.row.col.f32.bf16.bf16.f32 "
        "{%0,%1,%2,%3},{%4,%5,%6,%7},{%8,%9},{%0,%1,%2,%3};"
        : "+f"(c[0]), "+f"(c[1]), "+f"(c[2]), "+f"(c[3])
        : "r"(a0), "r"(a1), "r"(a2), "r"(a3), "r"(b0), "r"(b1));
}

__device__ __forceinline__ uint32_t pack2bf(float a, float b) {
    __nv_bfloat162 p = __floats2bfloat162_rn(a, b);
    return *(uint32_t*)&p;
}

// ---------------------------------------------------------------------------
// TF32 tensor-core GEMM, double-buffered (R6, proven)
// ---------------------------------------------------------------------------
__global__ __launch_bounds__(256, 2) void tgemm(
    const float* __restrict__ A,
    const float* __restrict__ B0, const float* __restrict__ B1,
    float* __restrict__ C0, float* __restrict__ C1,
    int M, int N, int K, int asel, int csel)
{
    const float* Bm = blockIdx.z ? B1 : B0;
    float* C = blockIdx.z ? C1 : C0;
    if (asel == 1) A = g_attn;
    if (csel == 1) C = g_q;

    __shared__ uint32_t As[2][16][136];
    __shared__ uint32_t Bs[2][16][136];

    int tid = threadIdx.x;
    int bn0 = blockIdx.x * 128, bm0 = blockIdx.y * 128;
    int warp = tid >> 5, lane = tid & 31;
    int wm = (warp & 1) * 64, wn = (warp >> 1) * 32;
    int lr = lane >> 2, lc = lane & 3;

    float acc[4][4][4];
#pragma unroll
    for (int mt = 0; mt < 4; mt++)
#pragma unroll
        for (int nt = 0; nt < 4; nt++)
#pragma unroll
            for (int i = 0; i < 4; i++) acc[mt][nt][i] = 0.f;

    int ar = tid >> 2, ac = (tid & 3) << 2;
    int br = tid >> 5, bc = (tid & 31) << 2;

    const float* Ap = A + (size_t)(bm0 + ar) * K + ac;
    const float* Bp = Bm + (size_t)br * N + bn0 + bc;

    {
        float4 a0v = *(const float4*)(Ap);
        float4 a1v = *(const float4*)(Ap + (size_t)64 * K);
        float4 b0v = *(const float4*)(Bp);
        float4 b1v = *(const float4*)(Bp + (size_t)8 * N);
        As[0][ac + 0][ar] = f2tf(a0v.x); As[0][ac + 1][ar] = f2tf(a0v.y);
        As[0][ac + 2][ar] = f2tf(a0v.z); As[0][ac + 3][ar] = f2tf(a0v.w);
        As[0][ac + 0][ar + 64] = f2tf(a1v.x); As[0][ac + 1][ar + 64] = f2tf(a1v.y);
        As[0][ac + 2][ar + 64] = f2tf(a1v.z); As[0][ac + 3][ar + 64] = f2tf(a1v.w);
        *(uint4*)&Bs[0][br][bc]     = make_uint4(f2tf(b0v.x), f2tf(b0v.y), f2tf(b0v.z), f2tf(b0v.w));
        *(uint4*)&Bs[0][br + 8][bc] = make_uint4(f2tf(b1v.x), f2tf(b1v.y), f2tf(b1v.z), f2tf(b1v.w));
    }
    __syncthreads();

    int nk = K >> 4;
    int p = 0;
    for (int t = 0; t < nk; t++) {
        float4 na0, na1, nb0, nb1;
        bool more = (t + 1 < nk);
        if (more) {
            Ap += 16;
            Bp += (size_t)16 * N;
            na0 = *(const float4*)(Ap);
            na1 = *(const float4*)(Ap + (size_t)64 * K);
            nb0 = *(const float4*)(Bp);
            nb1 = *(const float4*)(Bp + (size_t)8 * N);
        }

#pragma unroll
        for (int kk = 0; kk < 16; kk += 8) {
            uint32_t bf[4][2];
#pragma unroll
            for (int nt = 0; nt < 4; nt++) {
                bf[nt][0] = Bs[p][kk + lc][wn + nt * 8 + lr];
                bf[nt][1] = Bs[p][kk + lc + 4][wn + nt * 8 + lr];
            }
#pragma unroll
            for (int mt = 0; mt < 4; mt++) {
                uint32_t a0 = As[p][kk + lc][wm + mt * 16 + lr];
                uint32_t a1 = As[p][kk + lc][wm + mt * 16 + lr + 8];
                uint32_t a2 = As[p][kk + lc + 4][wm + mt * 16 + lr];
                uint32_t a3 = As[p][kk + lc + 4][wm + mt * 16 + lr + 8];
#pragma unroll
                for (int nt = 0; nt < 4; nt++)
                    mma8(acc[mt][nt], a0, a1, a2, a3, bf[nt][0], bf[nt][1]);
            }
        }

        if (more) {
            int q = p ^ 1;
            __syncthreads();
            As[q][ac + 0][ar] = f2tf(na0.x); As[q][ac + 1][ar] = f2tf(na0.y);
            As[q][ac + 2][ar] = f2tf(na0.z); As[q][ac + 3][ar] = f2tf(na0.w);
            As[q][ac + 0][ar + 64] = f2tf(na1.x); As[q][ac + 1][ar + 64] = f2tf(na1.y);
            As[q][ac + 2][ar + 64] = f2tf(na1.z); As[q][ac + 3][ar + 64] = f2tf(na1.w);
            *(uint4*)&Bs[q][br][bc]     = make_uint4(f2tf(nb0.x), f2tf(nb0.y), f2tf(nb0.z), f2tf(nb0.w));
            *(uint4*)&Bs[q][br + 8][bc] = make_uint4(f2tf(nb1.x), f2tf(nb1.y), f2tf(nb1.z), f2tf(nb1.w));
            __syncthreads();
            p = q;
        }
    }

#pragma unroll
    for (int mt = 0; mt < 4; mt++) {
        int row = bm0 + wm + mt * 16 + lr;
#pragma unroll
        for (int nt = 0; nt < 4; nt++) {
            int col = bn0 + wn + nt * 8 + lc * 2;
            *(float2*)&C[(size_t)row * N + col]       = make_float2(acc[mt][nt][0], acc[mt][nt][1]);
            *(float2*)&C[(size_t)(row + 8) * N + col] = make_float2(acc[mt][nt][2], acc[mt][nt][3]);
        }
    }
}

// ---------------------------------------------------------------------------
// RoPE + split kernels (run once; hoist all conversion out of flash)
// ---------------------------------------------------------------------------
__global__ __launch_bounds__(256) void rope_q_split()
{
    int idx = blockIdx.x * 256 + threadIdx.x;      // < B*T*H*64
    int j = idx & 63;
    int h = (idx >> 6) & (H_ - 1);
    int t = (idx >> 10) & (T_ - 1);
    int b = idx >> 21;
    const float scale = 0.08838834764831845f;      // 1/sqrt(128)
    float inv = powf(10000.0f, -(float)j * (1.0f / 64.0f));
    float ang = (float)t * inv;
    float sv, cv;
    sincosf(ang, &sv, &cv);
    size_t base = (((size_t)b * T_ + t) * H_ + h) * (size_t)HD_;
    float x1 = g_q[base + j], x2 = g_q[base + j + 64];
    float r1 = (x1 * cv - x2 * sv) * scale;
    float r2 = (x2 * cv + x1 * sv) * scale;
    __nv_bfloat16 h1 = __float2bfloat16(r1);
    __nv_bfloat16 h2 = __float2bfloat16(r2);
    g_qh[base + j] = h1;
    g_qh[base + j + 64] = h2;
    g_ql[base + j] = __float2bfloat16(r1 - __bfloat162float(h1));
    g_ql[base + j + 64] = __float2bfloat16(r2 - __bfloat162float(h2));
}

__global__ __launch_bounds__(256) void rope_k_split(float* __restrict__ kb)
{
    int idx = blockIdx.x * 256 + threadIdx.x;      // < B*T*64
    int j = idx & 63;
    int t = (idx >> 6) & (T_ - 1);
    int b = idx >> 17;
    float inv = powf(10000.0f, -(float)j * (1.0f / 64.0f));
    float ang = (float)t * inv;
    float sv, cv;
    sincosf(ang, &sv, &cv);
    size_t base = ((size_t)b * T_ + t) * (size_t)HD_;
    float x1 = kb[base + j], x2 = kb[base + j + 64];
    float r1 = x1 * cv - x2 * sv;
    float r2 = x2 * cv + x1 * sv;
    kb[base + j] = r1;              // present_k output (fp32)
    kb[base + j + 64] = r2;
    __nv_bfloat16 h1 = __float2bfloat16(r1);
    __nv_bfloat16 h2 = __float2bfloat16(r2);
    g_kh[base + j] = h1;
    g_kh[base + j + 64] = h2;
    g_kl[base + j] = __float2bfloat16(r1 - __bfloat162float(h1));
    g_kl[base + j + 64] = __float2bfloat16(r2 - __bfloat162float(h2));
}

// V: [B,T,HD] fp32 -> [B,HD,T] bf16 hi/lo (transpose + split)
__global__ void v_split_t(const float* __restrict__ vb)
{
    __shared__ float tile[32][33];
    int t0 = blockIdx.x * 32, d0 = blockIdx.y * 32, b = blockIdx.z;
    int tx = threadIdx.x, ty = threadIdx.y;
#pragma unroll
    for (int r = ty; r < 32; r += 8)
        tile[r][tx] = vb[((size_t)b * T_ + t0 + r) * HD_ + d0 + tx];
    __syncthreads();
#pragma unroll
    for (int r = ty; r < 32; r += 8) {
        float v = tile[tx][r];      // = V[t0+tx][d0+r]
        __nv_bfloat16 hh = __float2bfloat16(v);
        size_t o = ((size_t)b * HD_ + d0 + r) * T_ + t0 + tx;
        g_vth[o] = hh;
        g_vtl[o] = __float2bfloat16(v - __bfloat162float(hh));
    }
}

// ---------------------------------------------------------------------------
// Flash attention, bf16x3, preconverted inputs. BQ=BKV=64, 128 thr (4 warps).
// Q frags live in registers; K / V^T / P in smem (90KB -> 2 CTAs/SM).
// ---------------------------------------------------------------------------
#define FBQ 64
#define FBKV 64
#define KSTR 136      // halfs
#define VSTR 72       // halfs

__global__ __launch_bounds__(128, 2) void flash_bf16()
{
    extern __shared__ __nv_bfloat16 smh[];
    __nv_bfloat16* Kh  = smh;                  // [64][KSTR]
    __nv_bfloat16* Kl  = Kh + 64 * KSTR;
    __nv_bfloat16* VTh = Kl + 64 * KSTR;       // [128][VSTR]  (V^T: [d][kv])
    __nv_bfloat16* VTl = VTh + 128 * VSTR;
    __nv_bfloat16* Ph  = VTl + 128 * VSTR;     // [64][VSTR]
    __nv_bfloat16* Pl  = Ph + 64 * VSTR;

    int tid = threadIdx.x;
    int w = tid >> 5, lane = tid & 31;
    int lr = lane >> 2, lc = lane & 3;
    int qb = blockIdx.x;
    int bh = (int)blockIdx.y;
    int b = bh >> 4, h = bh & 15;
    int q0 = qb * FBQ;
    int rb = w * 16;

    // ---- Q fragments (hi/lo) in registers, loaded once ----
    uint32_t qfh[8][4], qfl[8][4];
    {
        const __nv_bfloat16* qh = g_qh + (((size_t)b * T_ + q0) * H_ + h) * (size_t)HD_;
        const __nv_bfloat16* ql = g_ql + (((size_t)b * T_ + q0) * H_ + h) * (size_t)HD_;
#pragma unroll
        for (int kk = 0; kk < 8; kk++) {
            int ke = kk * 16;
            qfh[kk][0] = *(const uint32_t*)&qh[(size_t)(rb + lr) * DIM_ + ke + 2 * lc];
            qfh[kk][1] = *(const uint32_t*)&qh[(size_t)(rb + lr + 8) * DIM_ + ke + 2 * lc];
            qfh[kk][2] = *(const uint32_t*)&qh[(size_t)(rb + lr) * DIM_ + ke + 2 * lc + 8];
            qfh[kk][3] = *(const uint32_t*)&qh[(size_t)(rb + lr + 8) * DIM_ + ke + 2 * lc + 8];
            qfl[kk][0] = *(const uint32_t*)&ql[(size_t)(rb + lr) * DIM_ + ke + 2 * lc];
            qfl[kk][1] = *(const uint32_t*)&ql[(size_t)(rb + lr + 8) * DIM_ + ke + 2 * lc];
            qfl[kk][2] = *(const uint32_t*)&ql[(size_t)(rb + lr) * DIM_ + ke + 2 * lc + 8];
            qfl[kk][3] = *(const uint32_t*)&ql[(size_t)(rb + lr + 8) * DIM_ + ke + 2 * lc + 8];
        }
    }

    float m0r = -1e30f, m1r = -1e30f, l0r = 0.f, l1r = 0.f;
    float O[16][4];
#pragma unroll
    for (int i = 0; i < 16; i++)
#pragma unroll
        for (int j = 0; j < 4; j++) O[i][j] = 0.f;

    const __nv_bfloat16* kbh = g_kh + (size_t)b * T_ * HD_;
    const __nv_bfloat16* kbl = g_kl + (size_t)b * T_ * HD_;
    const __nv_bfloat16* vbh = g_vth + (size_t)b * HD_ * T_;
    const __nv_bfloat16* vbl = g_vtl + (size_t)b * HD_ * T_;

    for (int kt = 0; kt <= qb; kt++) {
        int k0 = kt * FBKV;
        __syncthreads();   // protect K/V from overwrite while prior PV reads

        // ---- K tile: 64 rows x 128 halfs, hi+lo (uint4 = 8 halfs) ----
#pragma unroll
        for (int it = 0; it < 8; it++) {
            int i = tid + it * 128;                 // 1024 = 64 x 16 chunks
            int r = i >> 4, c = (i & 15) * 8;
            size_t ga = (size_t)(k0 + r) * HD_ + c;
            *(uint4*)&Kh[r * KSTR + c] = *(const uint4*)&kbh[ga];
            *(uint4*)&Kl[r * KSTR + c] = *(const uint4*)&kbl[ga];
        }
        // ---- V^T tile: 128 rows(d) x 64 halfs(kv), hi+lo ----
#pragma unroll
        for (int it = 0; it < 8; it++) {
            int i = tid + it * 128;                 // 1024 = 128 x 8 chunks
            int r = i >> 3, c = (i & 7) * 8;
            size_t ga = (size_t)r * T_ + k0 + c;
            *(uint4*)&VTh[r * VSTR + c] = *(const uint4*)&vbh[ga];
            *(uint4*)&VTl[r * VSTR + c] = *(const uint4*)&vbl[ga];
        }
        __syncthreads();

        // ---- S = Q @ K^T (bf16x3): rows rb..rb+15, cols 0..63 ----
        float sacc[8][4];
#pragma unroll
        for (int nt = 0; nt < 8; nt++)
#pragma unroll
            for (int j = 0; j < 4; j++) sacc[nt][j] = 0.f;

#pragma unroll
        for (int kk = 0; kk < 8; kk++) {
            int ke = kk * 16;
#pragma unroll
            for (int nt = 0; nt < 8; nt++) {
                int n = nt * 8 + lr;
                uint32_t bh0 = *(uint32_t*)&Kh[n * KSTR + ke + 2 * lc];
                uint32_t bh1 = *(uint32_t*)&Kh[n * KSTR + ke + 2 * lc + 8];
                uint32_t bl0 = *(uint32_t*)&Kl[n * KSTR + ke + 2 * lc];
                uint32_t bl1 = *(uint32_t*)&Kl[n * KSTR + ke + 2 * lc + 8];
                mmabf(sacc[nt], qfh[kk][0], qfh[kk][1], qfh[kk][2], qfh[kk][3], bh0, bh1);
                mmabf(sacc[nt], qfh[kk][0], qfh[kk][1], qfh[kk][2], qfh[kk][3], bl0, bl1);
                mmabf(sacc[nt], qfl[kk][0], qfl[kk][1], qfl[kk][2], qfl[kk][3], bh0, bh1);
            }
        }

        // ---- causal mask (diagonal tile only) ----
        if (kt == qb) {
            int r0g = rb + lr, r1g = r0g + 8;    // local == global offset (k0 == q0)
#pragma unroll
            for (int nt = 0; nt < 8; nt++) {
                int cg = nt * 8 + 2 * lc;
                if (cg > r0g)     sacc[nt][0] = -1e30f;
                if (cg + 1 > r0g) sacc[nt][1] = -1e30f;
                if (cg > r1g)     sacc[nt][2] = -1e30f;
                if (cg + 1 > r1g) sacc[nt][3] = -1e30f;
            }
        }

        // ---- online softmax (register state) ----
        float mt0 = -1e30f, mt1 = -1e30f;
#pragma unroll
        for (int nt = 0; nt < 8; nt++) {
            mt0 = fmaxf(mt0, fmaxf(sacc[nt][0], sacc[nt][1]));
            mt1 = fmaxf(mt1, fmaxf(sacc[nt][2], sacc[nt][3]));
        }
        mt0 = fmaxf(mt0, __shfl_xor_sync(0xffffffff, mt0, 1));
        mt0 = fmaxf(mt0, __shfl_xor_sync(0xffffffff, mt0, 2));
        mt1 = fmaxf(mt1, __shfl_xor_sync(0xffffffff, mt1, 1));
        mt1 = fmaxf(mt1, __shfl_xor_sync(0xffffffff, mt1, 2));

        float mn0 = fmaxf(m0r, mt0), mn1 = fmaxf(m1r, mt1);
        float al0f = __expf(m0r - mn0), al1f = __expf(m1r - mn1);
        m0r = mn0; m1r = mn1;

        float rs0 = 0.f, rs1 = 0.f;
#pragma unroll
        for (int nt = 0; nt < 8; nt++) {
            float p0 = __expf(sacc[nt][0] - mn0);
            float p1 = __expf(sacc[nt][1] - mn0);
            float p2 = __expf(sacc[nt][2] - mn1);
            float p3 = __expf(sacc[nt][3] - mn1);
            rs0 += p0 + p1; rs1 += p2 + p3;
            uint32_t h01 = pack2bf(p0, p1);
            uint32_t h23 = pack2bf(p2, p3);
            __nv_bfloat162 hb = *(__nv_bfloat162*)&h01;
            __nv_bfloat162 hb2 = *(__nv_bfloat162*)&h23;
            uint32_t l01 = pack2bf(p0 - __bfloat162float(hb.x), p1 - __bfloat162float(hb.y));
            uint32_t l23 = pack2bf(p2 - __bfloat162float(hb2.x), p3 - __bfloat162float(hb2.y));
            *(uint32_t*)&Ph[(rb + lr) * VSTR + nt * 8 + 2 * lc]     = h01;
            *(uint32_t*)&Ph[(rb + lr + 8) * VSTR + nt * 8 + 2 * lc] = h23;
            *(uint32_t*)&Pl[(rb + lr) * VSTR + nt * 8 + 2 * lc]     = l01;
            *(uint32_t*)&Pl[(rb + lr + 8) * VSTR + nt * 8 + 2 * lc] = l23;
        }
        rs0 += __shfl_xor_sync(0xffffffff, rs0, 1);
        rs0 += __shfl_xor_sync(0xffffffff, rs0, 2);
        rs1 += __shfl_xor_sync(0xffffffff, rs1, 1);
        rs1 += __shfl_xor_sync(0xffffffff, rs1, 2);
        l0r = l0r * al0f + rs0;
        l1r = l1r * al1f + rs1;

#pragma unroll
        for (int nt = 0; nt < 16; nt++) {
            O[nt][0] *= al0f; O[nt][1] *= al0f;
            O[nt][2] *= al1f; O[nt][3] *= al1f;
        }
        __syncwarp();   // P rows are warp-private; warp-level visibility only

        // ---- O += P @ V (bf16x3) ----
#pragma unroll
        for (int kk = 0; kk < 4; kk++) {
            int ke = kk * 16;
            uint32_t ah0 = *(uint32_t*)&Ph[(rb + lr) * VSTR + ke + 2 * lc];
            uint32_t ah1 = *(uint32_t*)&Ph[(rb + lr + 8) * VSTR + ke + 2 * lc];
            uint32_t ah2 = *(uint32_t*)&Ph[(rb + lr) * VSTR + ke + 2 * lc + 8];
            uint32_t ah3 = *(uint32_t*)&Ph[(rb + lr + 8) * VSTR + ke + 2 * lc + 8];
            uint32_t al0 = *(uint32_t*)&Pl[(rb + lr) * VSTR + ke + 2 * lc];
            uint32_t al1 = *(uint32_t*)&Pl[(rb + lr + 8) * VSTR + ke + 2 * lc];
            uint32_t al2 = *(uint32_t*)&Pl[(rb + lr) * VSTR + ke + 2 * lc + 8];
            uint32_t al3 = *(uint32_t*)&Pl[(rb + lr + 8) * VSTR + ke + 2 * lc + 8];
#pragma unroll
            for (int nt = 0; nt < 16; nt++) {
                int n = nt * 8 + lr;
                uint32_t bh0 = *(uint32_t*)&VTh[n * VSTR + ke + 2 * lc];
                uint32_t bh1 = *(uint32_t*)&VTh[n * VSTR + ke + 2 * lc + 8];
                uint32_t bl0 = *(uint32_t*)&VTl[n * VSTR + ke + 2 * lc];
                uint32_t bl1 = *(uint32_t*)&VTl[n * VSTR + ke + 2 * lc + 8];
                mmabf(O[nt], ah0, ah1, ah2, ah3, bh0, bh1);
                mmabf(O[nt], ah0, ah1, ah2, ah3, bl0, bl1);
                mmabf(O[nt], al0, al1, al2, al3, bh0, bh1);
            }
        }
    }

    // ---- finalize: O / l -> g_attn [B,T,DIM] ----
    float inv0 = 1.f / l0r, inv1 = 1.f / l1r;
    float* ob = g_attn + (((size_t)b * T_ + q0) * H_ + h) * (size_t)HD_;
#pragma unroll
    for (int nt = 0; nt < 16; nt++) {
        int col = nt * 8 + 2 * lc;
        *(float2*)&ob[(size_t)(rb + lr) * DIM_ + col] =
            make_float2(O[nt][0] * inv0, O[nt][1] * inv0);
        *(float2*)&ob[(size_t)(rb + lr + 8) * DIM_ + col] =
            make_float2(O[nt][2] * inv1, O[nt][3] * inv1);
    }
}

static const int FLASH_SMEM = (2 * 64 * KSTR + 2 * 128 * VSTR + 2 * 64 * VSTR) * 2;

// ---------------------------------------------------------------------------
extern "C" void kernel_launch(void* const* d_in, const int* in_sizes, int n_in,
                              void* d_out, int out_size)
{
    const float* x  = (const float*)d_in[0];
    const float* Wq = (const float*)d_in[1];
    const float* Wk = (const float*)d_in[2];
    const float* Wv = (const float*)d_in[3];
    const float* Wo = (const float*)d_in[4];

    float* out = (float*)d_out;                       // [B,T,DIM]
    float* pk  = out + (size_t)BT_ * DIM_;            // present_k [B,1,T,HD]
    float* pv  = pk + (size_t)BT_ * HD_;              // present_v [B,1,T,HD]

    cudaFuncSetAttribute(flash_bf16, cudaFuncAttributeMaxDynamicSharedMemorySize, FLASH_SMEM);

    dim3 blk(256);
    // Q = x @ Wq -> g_q
    tgemm<<<dim3(DIM_ / 128, BT_ / 128, 1), blk>>>(x, Wq, Wq, nullptr, nullptr,
                                                   BT_, DIM_, DIM_, 0, 1);
    // K,V fused: z=0 -> (Wk, pk), z=1 -> (Wv, pv)
    tgemm<<<dim3(1, BT_ / 128, 2), blk>>>(x, Wk, Wv, pk, pv, BT_, HD_, DIM_, 0, 0);

    // RoPE + bf16 hi/lo pre-split (+ V transpose)
    rope_q_split<<<(BT_ * H_ * 64) / 256, blk>>>();
    rope_k_split<<<(BT_ * 64) / 256, blk>>>(pk);
    v_split_t<<<dim3(T_ / 32, HD_ / 32, B_), dim3(32, 8)>>>(pv);

    // Attention -> g_attn
    flash_bf16<<<dim3(T_ / FBQ, B_ * H_), 128, FLASH_SMEM>>>();

    // out = attn @ Wo
    tgemm<<<dim3(DIM_ / 128, BT_ / 128, 1), blk>>>(nullptr, Wo, Wo, out, out,
                                                   BT_, DIM_, DIM_, 1, 0);
}